// round 5
// baseline (speedup 1.0000x reference)
#include <cuda_runtime.h>
#include <math.h>

#define N_PTS  32768
#define N_DIM  8
#define OP1    25      // order + 1
#define N_PERM 32
#define KP     13      // ceil(26/2) f32x2 pairs per vector
#define KROW   14      // padded pairs per smem weight row (112B, 16B-aligned rows)

typedef unsigned long long ull;

struct Sc2   { float v[28]; };
struct Binom { float b[28]; };

// Bernstein basis scratch, pair-packed: [(d*KP + kk)*N_PTS + n] -> (B[2kk], B[2kk+1])
__device__ float2 g_Bt [N_DIM * KP * N_PTS];
// Squared basis for the var chain (same layout)
__device__ float2 g_Bt2[N_DIM * KP * N_PTS];

// ---------------- packed f32x2 helpers ----------------
__device__ __forceinline__ ull pk2(float l, float h) {
    ull r; asm("mov.b64 %0, {%1, %2};" : "=l"(r) : "f"(l), "f"(h)); return r;
}
__device__ __forceinline__ float lo2(ull a) {
    float l, h; asm("mov.b64 {%0, %1}, %2;" : "=f"(l), "=f"(h) : "l"(a)); return l;
}
__device__ __forceinline__ float hi2(ull a) {
    float l, h; asm("mov.b64 {%0, %1}, %2;" : "=f"(l), "=f"(h) : "l"(a)); return h;
}
__device__ __forceinline__ ull dup2(float x) { return pk2(x, x); }
__device__ __forceinline__ ull fma2(ull a, ull b, ull c) {
    ull d; asm("fma.rn.f32x2 %0, %1, %2, %3;" : "=l"(d) : "l"(a), "l"(b), "l"(c)); return d;
}
__device__ __forceinline__ ull mul2(ull a, ull b) {
    ull d; asm("mul.rn.f32x2 %0, %1, %2;" : "=l"(d) : "l"(a), "l"(b)); return d;
}
__device__ __forceinline__ ull add2(ull a, ull b) {
    ull d; asm("add.rn.f32x2 %0, %1, %2;" : "=l"(d) : "l"(a), "l"(b)); return d;
}
__device__ __forceinline__ void prefetchL1(const void* p) {
    asm volatile("prefetch.global.L1 [%0];" :: "l"(p));
}

// ---------------- pre-kernel: Bernstein basis (+squares) + output zero-init ----
__global__ void bern_prep_kernel(const float* __restrict__ X,
                                 float* __restrict__ out, Binom bn)
{
    const int idx = blockIdx.x * blockDim.x + threadIdx.x;   // over N_DIM*N_PTS
    if (idx < 2 * N_PTS) out[idx] = 0.0f;                    // zero d_out (poisoned)
    if (idx >= N_DIM * N_PTS) return;
    const int d = idx >> 15;            // idx / 32768
    const int n = idx & (N_PTS - 1);

    const float x = X[n * N_DIM + d];
    const float q = 1.0f - x;

    float xpk[OP1];
    float xp = 1.0f;
    #pragma unroll
    for (int k = 0; k < OP1; k++) { xpk[k] = xp; xp *= x; }

    float B[26];
    float qp = 1.0f;
    #pragma unroll
    for (int k = OP1 - 1; k >= 0; k--) { B[k] = bn.b[k] * xpk[k] * qp; qp *= q; }
    B[25] = 0.0f;

    #pragma unroll
    for (int kk = 0; kk < KP; kk++) {
        const float a = B[2*kk], b = B[2*kk + 1];
        g_Bt [(d * KP + kk) * N_PTS + n] = make_float2(a, b);
        g_Bt2[(d * KP + kk) * N_PTS + n] = make_float2(a * a, b * b);
    }
}

// ---------------- main kernel: one chain (mean or var) per block, 2 pts/thread ----
// blockIdx.z == 0: mean chain   v <- (v @ W) * B              -> out col 0
// blockIdx.z == 1: var chain    v <- (v @ (exp(W)*sc2)) * B^2 -> out col 1 (/post_prec)
__global__ __launch_bounds__(128, 4)
void bern_chain_kernel(const int*   __restrict__ perm,
                       const float* __restrict__ mw0,
                       const float* __restrict__ mwr,
                       const float* __restrict__ vw0,
                       const float* __restrict__ vwr,
                       const float* __restrict__ postp,
                       float*       __restrict__ out,
                       Sc2 sc2)
{
    __shared__ alignas(16) ull sW[7 * 25 * KROW];
    __shared__ alignas(16) ull sw0[KROW];
    __shared__ int   sperm[8];
    __shared__ float sscale;

    const int p   = blockIdx.y;
    const int VAR = blockIdx.z;
    const int tid = threadIdx.x;

    const float* __restrict__ w0g = VAR ? vw0 : mw0;
    const float* __restrict__ wrg = VAR ? vwr : mwr;
    // var chain reads pre-squared basis; mean reads plain basis
    const float2* __restrict__ gB = VAR ? g_Bt2 : g_Bt;

    // Cooperative weight load; var chain applies exp(w)*sc2[k]; pad k>=25 with 0.
    {
        float* fW = (float*)sW;
        for (int t = tid; t < 7 * 25 * 2 * KROW; t += 128) {
            const int k  = t % (2 * KROW);
            const int rj = t / (2 * KROW);
            const int j  = rj % 25;
            const int s  = rj / 25;
            float w = 0.0f;
            if (k < OP1) {
                const int gi = ((s * N_PERM + p) * OP1 + j) * OP1 + k;
                w = VAR ? expf(wrg[gi]) * sc2.v[k] : wrg[gi];
            }
            fW[t] = w;
        }
        if (tid < 2 * KROW) {
            float w = 0.0f;
            if (tid < OP1)
                w = VAR ? expf(w0g[p * OP1 + tid]) * sc2.v[tid] : w0g[p * OP1 + tid];
            ((float*)sw0)[tid] = w;
        }
        if (tid < 8)  sperm[tid] = perm[p * 8 + tid];
        if (tid == 0) sscale = VAR ? 1.0f / postp[p] : 1.0f;
    }
    __syncthreads();

    // Adjacent point pairing: one LDG.128 per kk serves both points; both points
    // share one 128B line, so one prefetch covers both.
    const int n0 = blockIdx.x * 256 + 2 * tid;   // even; n1 = n0 + 1

    ull v0[KP], v1[KP];

    // stage 0
    {
        const float2* bp = gB + sperm[0] * (KP * N_PTS) + n0;   // 32-bit index math
        #pragma unroll
        for (int kk = 0; kk < KP; kk++) {
            const ulonglong2 bb = *(const ulonglong2*)(bp + kk * N_PTS);
            v0[kk] = mul2(sw0[kk], bb.x);
            v1[kk] = mul2(sw0[kk], bb.y);
        }
    }

    // stages 1..7 (rolled over s to stay inside I$)
    #pragma unroll 1
    for (int s = 0; s < 7; s++) {
        const float2* bp = gB + sperm[s + 1] * (KP * N_PTS) + n0;

        // prefetch this stage's basis lines into L1; consumed at the epilogue,
        // ~950 issue-cycles from now — removes the cold-LDG batch stall.
        #pragma unroll
        for (int kk = 0; kk < KP; kk++)
            prefetchL1(bp + kk * N_PTS);

        ull acc0[KP], acc1[KP];
        #pragma unroll
        for (int kk = 0; kk < KP; kk++) { acc0[kk] = 0ULL; acc1[kk] = 0ULL; }

        const ull* base = sW + s * 25 * KROW;

        #pragma unroll
        for (int j = 0; j < 25; j++) {
            const float a0 = (j & 1) ? hi2(v0[j >> 1]) : lo2(v0[j >> 1]);
            const float a1 = (j & 1) ? hi2(v1[j >> 1]) : lo2(v1[j >> 1]);
            const ull vj0 = dup2(a0);
            const ull vj1 = dup2(a1);
            const ull* rw = base + j * KROW;
            #pragma unroll
            for (int h = 0; h < 7; h++) {
                const ulonglong2 w = *(const ulonglong2*)(rw + 2 * h);
                acc0[2*h] = fma2(vj0, w.x, acc0[2*h]);
                acc1[2*h] = fma2(vj1, w.x, acc1[2*h]);
                if (2*h + 1 < KP) {
                    acc0[2*h + 1] = fma2(vj0, w.y, acc0[2*h + 1]);
                    acc1[2*h + 1] = fma2(vj1, w.y, acc1[2*h + 1]);
                }
            }
        }

        // apply basis (b pre-squared for var chain; loads hit L1 via prefetch)
        #pragma unroll
        for (int kk = 0; kk < KP; kk++) {
            const ulonglong2 bb = *(const ulonglong2*)(bp + kk * N_PTS);
            v0[kk] = mul2(acc0[kk], bb.x);
            v1[kk] = mul2(acc1[kk], bb.y);
        }
    }

    // reduce over k, then over p via atomics
    ull s0 = v0[0], s1 = v1[0];
    #pragma unroll
    for (int kk = 1; kk < KP; kk++) { s0 = add2(s0, v0[kk]); s1 = add2(s1, v1[kk]); }
    const float r0 = (lo2(s0) + hi2(s0)) * sscale;
    const float r1 = (lo2(s1) + hi2(s1)) * sscale;

    atomicAdd(out + 2 * n0 + VAR, r0);
    atomicAdd(out + 2 * (n0 + 1) + VAR, r1);
}

// ---------------- host: sc2 = inv(B(I)^2) @ ones in double ----------------
static void compute_binom_d(double* bn) {
    bn[0] = 1.0;
    for (int k = 0; k < 24; k++) bn[k + 1] = bn[k] * (double)(24 - k) / (double)(k + 1);
}

static void compute_sc2_d(const double* bn, double* y) {
    double A[25][26];
    for (int i = 0; i < 25; i++) {
        const double t = (double)i / 24.0;
        const double q = 1.0 - t;
        double xp[25], qp[25];
        xp[0] = 1.0; for (int k = 1; k < 25; k++) xp[k] = xp[k - 1] * t;
        qp[0] = 1.0; for (int k = 1; k < 25; k++) qp[k] = qp[k - 1] * q;
        for (int k = 0; k < 25; k++) {
            const double B = bn[k] * xp[k] * qp[24 - k];
            A[i][k] = B * B;
        }
        A[i][25] = 1.0;   // rhs = ones
    }
    for (int c = 0; c < 25; c++) {
        int piv = c;
        for (int r = c + 1; r < 25; r++)
            if (fabs(A[r][c]) > fabs(A[piv][c])) piv = r;
        if (piv != c)
            for (int k = c; k < 26; k++) { double tmp = A[c][k]; A[c][k] = A[piv][k]; A[piv][k] = tmp; }
        const double inv = 1.0 / A[c][c];
        for (int r = 0; r < 25; r++) {
            if (r == c) continue;
            const double f = A[r][c] * inv;
            for (int k = c; k < 26; k++) A[r][k] -= f * A[c][k];
        }
    }
    for (int i = 0; i < 25; i++) y[i] = A[i][25] / A[i][i];
}

extern "C" void kernel_launch(void* const* d_in, const int* in_sizes, int n_in,
                              void* d_out, int out_size)
{
    const float* X    = (const float*)d_in[0];   // Xnew      (N, 8)
    const int*   perm = (const int*)  d_in[1];   // perm      (32, 8)
    const float* mw0  = (const float*)d_in[2];   // meanw0    (32, 1, 25)
    const float* mwr  = (const float*)d_in[3];   // meanw_rest(7, 32, 25, 25)
    const float* vw0  = (const float*)d_in[4];   // varw0     (32, 1, 25)
    const float* vwr  = (const float*)d_in[5];   // varw_rest (7, 32, 25, 25)
    const float* pp   = (const float*)d_in[6];   // post_prec (32,)
    float* out = (float*)d_out;                  // (N, 2) float32

    double bn_d[25], sc2_d[25];
    compute_binom_d(bn_d);
    compute_sc2_d(bn_d, sc2_d);

    Binom bn = {};
    Sc2   sc = {};
    for (int k = 0; k < 25; k++) {
        bn.b[k] = (float)bn_d[k];
        sc.v[k] = (float)sc2_d[k];
    }

    bern_prep_kernel<<<(N_DIM * N_PTS) / 256, 256>>>(X, out, bn);

    dim3 grid(N_PTS / 256, N_PERM, 2);
    bern_chain_kernel<<<grid, 128>>>(perm, mw0, mwr, vw0, vwr, pp, out, sc);
}

// round 7
// speedup vs baseline: 1.0787x; 1.0787x over previous
#include <cuda_runtime.h>
#include <math.h>

#define N_PTS  32768
#define N_DIM  8
#define OP1    25      // order + 1
#define N_PERM 32
#define KP     13      // ceil(26/2) f32x2 pairs per vector
#define KROW   14      // padded pairs per smem weight row (112B, 16B-aligned rows)

typedef unsigned long long ull;

struct Sc2   { float v[28]; };
struct Binom { float b[28]; };

// Bernstein basis scratch, pair-packed: [(d*KP + kk)*N_PTS + n] -> (B[2kk], B[2kk+1])
__device__ float2 g_Bt [N_DIM * KP * N_PTS];
// Squared basis for the var chain (same layout)
__device__ float2 g_Bt2[N_DIM * KP * N_PTS];

// ---------------- packed f32x2 helpers ----------------
__device__ __forceinline__ ull pk2(float l, float h) {
    ull r; asm("mov.b64 %0, {%1, %2};" : "=l"(r) : "f"(l), "f"(h)); return r;
}
__device__ __forceinline__ float lo2(ull a) {
    float l, h; asm("mov.b64 {%0, %1}, %2;" : "=f"(l), "=f"(h) : "l"(a)); return l;
}
__device__ __forceinline__ float hi2(ull a) {
    float l, h; asm("mov.b64 {%0, %1}, %2;" : "=f"(l), "=f"(h) : "l"(a)); return h;
}
__device__ __forceinline__ ull dup2(float x) { return pk2(x, x); }
__device__ __forceinline__ ull fma2(ull a, ull b, ull c) {
    ull d; asm("fma.rn.f32x2 %0, %1, %2, %3;" : "=l"(d) : "l"(a), "l"(b), "l"(c)); return d;
}
__device__ __forceinline__ ull mul2(ull a, ull b) {
    ull d; asm("mul.rn.f32x2 %0, %1, %2;" : "=l"(d) : "l"(a), "l"(b)); return d;
}
__device__ __forceinline__ ull add2(ull a, ull b) {
    ull d; asm("add.rn.f32x2 %0, %1, %2;" : "=l"(d) : "l"(a), "l"(b)); return d;
}

// ---------------- pre-kernel: Bernstein basis (+squares) + output zero-init ----
__global__ void bern_prep_kernel(const float* __restrict__ X,
                                 float* __restrict__ out, Binom bn)
{
    const int idx = blockIdx.x * blockDim.x + threadIdx.x;   // over N_DIM*N_PTS
    if (idx < 2 * N_PTS) out[idx] = 0.0f;                    // zero d_out (poisoned)
    if (idx >= N_DIM * N_PTS) return;
    const int d = idx >> 15;            // idx / 32768
    const int n = idx & (N_PTS - 1);

    const float x = X[n * N_DIM + d];
    const float q = 1.0f - x;

    float xpk[OP1];
    float xp = 1.0f;
    #pragma unroll
    for (int k = 0; k < OP1; k++) { xpk[k] = xp; xp *= x; }

    float B[26];
    float qp = 1.0f;
    #pragma unroll
    for (int k = OP1 - 1; k >= 0; k--) { B[k] = bn.b[k] * xpk[k] * qp; qp *= q; }
    B[25] = 0.0f;

    #pragma unroll
    for (int kk = 0; kk < KP; kk++) {
        const float a = B[2*kk], b = B[2*kk + 1];
        g_Bt [(d * KP + kk) * N_PTS + n] = make_float2(a, b);
        g_Bt2[(d * KP + kk) * N_PTS + n] = make_float2(a * a, b * b);
    }
}

// ---------------- main kernel: one chain (mean or var) per block, 2 pts/thread ----
// blockIdx.z == 0: mean chain   v <- (v @ W) * B              -> out col 0
// blockIdx.z == 1: var chain    v <- (v @ (exp(W)*sc2)) * B^2 -> out col 1 (/post_prec)
__global__ __launch_bounds__(128, 4)
void bern_chain_kernel(const int*   __restrict__ perm,
                       const float* __restrict__ mw0,
                       const float* __restrict__ mwr,
                       const float* __restrict__ vw0,
                       const float* __restrict__ vwr,
                       const float* __restrict__ postp,
                       float*       __restrict__ out,
                       Sc2 sc2)
{
    __shared__ alignas(16) ull sW[7 * 25 * KROW];
    __shared__ alignas(16) ull sw0[KROW];
    __shared__ int   sperm[8];
    __shared__ float sscale;

    const int p   = blockIdx.y;
    const int VAR = blockIdx.z;
    const int tid = threadIdx.x;

    const float* __restrict__ w0g = VAR ? vw0 : mw0;
    const float* __restrict__ wrg = VAR ? vwr : mwr;
    // var chain reads pre-squared basis; mean reads plain basis
    const float2* __restrict__ gB = VAR ? g_Bt2 : g_Bt;

    // Adjacent point pairing: one LDG.128 per kk serves both points.
    const int n0 = blockIdx.x * 256 + 2 * tid;   // even; n1 = n0 + 1

    // --- issue stage-0 basis loads FIRST, overlapping with weight staging ---
    ulonglong2 bbv[KP];
    {
        const int d0 = perm[p * 8];                      // broadcast LDG
        const float2* bp0 = gB + d0 * (KP * N_PTS) + n0;
        #pragma unroll
        for (int kk = 0; kk < KP; kk++)
            bbv[kk] = *(const ulonglong2*)(bp0 + kk * N_PTS);
    }

    // Cooperative weight load; var chain applies exp(w)*sc2[k]; pad k>=25 with 0.
    {
        float* fW = (float*)sW;
        for (int t = tid; t < 7 * 25 * 2 * KROW; t += 128) {
            const int k  = t % (2 * KROW);
            const int rj = t / (2 * KROW);
            const int j  = rj % 25;
            const int s  = rj / 25;
            float w = 0.0f;
            if (k < OP1) {
                const int gi = ((s * N_PERM + p) * OP1 + j) * OP1 + k;
                w = VAR ? expf(wrg[gi]) * sc2.v[k] : wrg[gi];
            }
            fW[t] = w;
        }
        if (tid < 2 * KROW) {
            float w = 0.0f;
            if (tid < OP1)
                w = VAR ? expf(w0g[p * OP1 + tid]) * sc2.v[tid] : w0g[p * OP1 + tid];
            ((float*)sw0)[tid] = w;
        }
        if (tid < 8)  sperm[tid] = perm[p * 8 + tid];
        if (tid == 0) sscale = VAR ? 1.0f / postp[p] : 1.0f;
    }
    __syncthreads();

    ull v0[KP], v1[KP];

    // stage 0 (basis already resident in bbv)
    #pragma unroll
    for (int kk = 0; kk < KP; kk++) {
        v0[kk] = mul2(sw0[kk], bbv[kk].x);
        v1[kk] = mul2(sw0[kk], bbv[kk].y);
    }

    // stages 1..7 (rolled over s to stay inside I$)
    #pragma unroll 1
    for (int s = 0; s < 7; s++) {
        const float2* bp = gB + sperm[s + 1] * (KP * N_PTS) + n0;

        ull acc0[KP], acc1[KP];
        #pragma unroll
        for (int kk = 0; kk < KP; kk++) { acc0[kk] = 0ULL; acc1[kk] = 0ULL; }

        const ull* base = sW + s * 25 * KROW;

        #pragma unroll
        for (int j = 0; j < 25; j++) {
            // Hoisted epilogue loads: by j==13 half the v registers are dead, so
            // bbv fits; the loads get ~12 j-iterations of lead to cover L2 latency.
            if (j == 13) {
                #pragma unroll
                for (int kk = 0; kk < KP; kk++)
                    bbv[kk] = *(const ulonglong2*)(bp + kk * N_PTS);
            }
            const float a0 = (j & 1) ? hi2(v0[j >> 1]) : lo2(v0[j >> 1]);
            const float a1 = (j & 1) ? hi2(v1[j >> 1]) : lo2(v1[j >> 1]);
            const ull vj0 = dup2(a0);
            const ull vj1 = dup2(a1);
            const ull* rw = base + j * KROW;
            #pragma unroll
            for (int h = 0; h < 7; h++) {
                const ulonglong2 w = *(const ulonglong2*)(rw + 2 * h);
                acc0[2*h] = fma2(vj0, w.x, acc0[2*h]);
                acc1[2*h] = fma2(vj1, w.x, acc1[2*h]);
                if (2*h + 1 < KP) {
                    acc0[2*h + 1] = fma2(vj0, w.y, acc0[2*h + 1]);
                    acc1[2*h + 1] = fma2(vj1, w.y, acc1[2*h + 1]);
                }
            }
        }

        // apply basis (registers already in flight from the j==13 hoist)
        #pragma unroll
        for (int kk = 0; kk < KP; kk++) {
            v0[kk] = mul2(acc0[kk], bbv[kk].x);
            v1[kk] = mul2(acc1[kk], bbv[kk].y);
        }
    }

    // reduce over k, then over p via atomics
    ull s0 = v0[0], s1 = v1[0];
    #pragma unroll
    for (int kk = 1; kk < KP; kk++) { s0 = add2(s0, v0[kk]); s1 = add2(s1, v1[kk]); }
    const float r0 = (lo2(s0) + hi2(s0)) * sscale;
    const float r1 = (lo2(s1) + hi2(s1)) * sscale;

    atomicAdd(out + 2 * n0 + VAR, r0);
    atomicAdd(out + 2 * (n0 + 1) + VAR, r1);
}

// ---------------- host: sc2 = inv(B(I)^2) @ ones in double ----------------
static void compute_binom_d(double* bn) {
    bn[0] = 1.0;
    for (int k = 0; k < 24; k++) bn[k + 1] = bn[k] * (double)(24 - k) / (double)(k + 1);
}

static void compute_sc2_d(const double* bn, double* y) {
    double A[25][26];
    for (int i = 0; i < 25; i++) {
        const double t = (double)i / 24.0;
        const double q = 1.0 - t;
        double xp[25], qp[25];
        xp[0] = 1.0; for (int k = 1; k < 25; k++) xp[k] = xp[k - 1] * t;
        qp[0] = 1.0; for (int k = 1; k < 25; k++) qp[k] = qp[k - 1] * q;
        for (int k = 0; k < 25; k++) {
            const double B = bn[k] * xp[k] * qp[24 - k];
            A[i][k] = B * B;
        }
        A[i][25] = 1.0;   // rhs = ones
    }
    for (int c = 0; c < 25; c++) {
        int piv = c;
        for (int r = c + 1; r < 25; r++)
            if (fabs(A[r][c]) > fabs(A[piv][c])) piv = r;
        if (piv != c)
            for (int k = c; k < 26; k++) { double tmp = A[c][k]; A[c][k] = A[piv][k]; A[piv][k] = tmp; }
        const double inv = 1.0 / A[c][c];
        for (int r = 0; r < 25; r++) {
            if (r == c) continue;
            const double f = A[r][c] * inv;
            for (int k = c; k < 26; k++) A[r][k] -= f * A[c][k];
        }
    }
    for (int i = 0; i < 25; i++) y[i] = A[i][25] / A[i][i];
}

extern "C" void kernel_launch(void* const* d_in, const int* in_sizes, int n_in,
                              void* d_out, int out_size)
{
    const float* X    = (const float*)d_in[0];   // Xnew      (N, 8)
    const int*   perm = (const int*)  d_in[1];   // perm      (32, 8)
    const float* mw0  = (const float*)d_in[2];   // meanw0    (32, 1, 25)
    const float* mwr  = (const float*)d_in[3];   // meanw_rest(7, 32, 25, 25)
    const float* vw0  = (const float*)d_in[4];   // varw0     (32, 1, 25)
    const float* vwr  = (const float*)d_in[5];   // varw_rest (7, 32, 25, 25)
    const float* pp   = (const float*)d_in[6];   // post_prec (32,)
    float* out = (float*)d_out;                  // (N, 2) float32

    double bn_d[25], sc2_d[25];
    compute_binom_d(bn_d);
    compute_sc2_d(bn_d, sc2_d);

    Binom bn = {};
    Sc2   sc = {};
    for (int k = 0; k < 25; k++) {
        bn.b[k] = (float)bn_d[k];
        sc.v[k] = (float)sc2_d[k];
    }

    bern_prep_kernel<<<(N_DIM * N_PTS) / 256, 256>>>(X, out, bn);

    dim3 grid(N_PTS / 256, N_PERM, 2);
    bern_chain_kernel<<<grid, 128>>>(perm, mw0, mwr, vw0, vwr, pp, out, sc);
}

// round 8
// speedup vs baseline: 1.3797x; 1.2790x over previous
#include <cuda_runtime.h>
#include <math.h>

#define N_PTS  32768
#define N_DIM  8
#define OP1    25      // order + 1
#define N_PERM 32
#define KP     13      // ceil(26/2) f32x2 pairs per vector
#define KROW   14      // padded pairs per smem weight row (112B, 16B-aligned rows)
#define WSTRIDE (7 * 25 * 2 * KROW)   // floats per permutation = 4900

typedef unsigned long long ull;

struct Sc2   { float v[28]; };
struct Binom { float b[28]; };

// Bernstein basis scratch, pair-packed: [(d*KP + kk)*N_PTS + n] -> (B[2kk], B[2kk+1])
__device__ float2 g_Bt [N_DIM * KP * N_PTS];
// Squared basis for the var chain (same layout)
__device__ float2 g_Bt2[N_DIM * KP * N_PTS];
// Pre-transformed weights in final smem layout [p][s][j][28]:
__device__ float g_Wm[N_PERM * WSTRIDE];   // mean: padded copy
__device__ float g_Wv[N_PERM * WSTRIDE];   // var:  exp(w)*sc2, padded
__device__ float g_w0m[N_PERM * 28];
__device__ float g_w0v[N_PERM * 28];

// ---------------- packed f32x2 helpers ----------------
__device__ __forceinline__ ull pk2(float l, float h) {
    ull r; asm("mov.b64 %0, {%1, %2};" : "=l"(r) : "f"(l), "f"(h)); return r;
}
__device__ __forceinline__ float lo2(ull a) {
    float l, h; asm("mov.b64 {%0, %1}, %2;" : "=f"(l), "=f"(h) : "l"(a)); return l;
}
__device__ __forceinline__ float hi2(ull a) {
    float l, h; asm("mov.b64 {%0, %1}, %2;" : "=f"(l), "=f"(h) : "l"(a)); return h;
}
__device__ __forceinline__ ull dup2(float x) { return pk2(x, x); }
__device__ __forceinline__ ull fma2(ull a, ull b, ull c) {
    ull d; asm("fma.rn.f32x2 %0, %1, %2, %3;" : "=l"(d) : "l"(a), "l"(b), "l"(c)); return d;
}
__device__ __forceinline__ ull mul2(ull a, ull b) {
    ull d; asm("mul.rn.f32x2 %0, %1, %2;" : "=l"(d) : "l"(a), "l"(b)); return d;
}
__device__ __forceinline__ ull add2(ull a, ull b) {
    ull d; asm("add.rn.f32x2 %0, %1, %2;" : "=l"(d) : "l"(a), "l"(b)); return d;
}

// ---------------- pre-kernel 1: Bernstein basis (+squares) + output zero-init ----
__global__ void bern_prep_kernel(const float* __restrict__ X,
                                 float* __restrict__ out, Binom bn)
{
    const int idx = blockIdx.x * blockDim.x + threadIdx.x;   // over N_DIM*N_PTS
    if (idx < 2 * N_PTS) out[idx] = 0.0f;                    // zero d_out (poisoned)
    if (idx >= N_DIM * N_PTS) return;
    const int d = idx >> 15;            // idx / 32768
    const int n = idx & (N_PTS - 1);

    const float x = X[n * N_DIM + d];
    const float q = 1.0f - x;

    float xpk[OP1];
    float xp = 1.0f;
    #pragma unroll
    for (int k = 0; k < OP1; k++) { xpk[k] = xp; xp *= x; }

    float B[26];
    float qp = 1.0f;
    #pragma unroll
    for (int k = OP1 - 1; k >= 0; k--) { B[k] = bn.b[k] * xpk[k] * qp; qp *= q; }
    B[25] = 0.0f;

    #pragma unroll
    for (int kk = 0; kk < KP; kk++) {
        const float a = B[2*kk], b = B[2*kk + 1];
        g_Bt [(d * KP + kk) * N_PTS + n] = make_float2(a, b);
        g_Bt2[(d * KP + kk) * N_PTS + n] = make_float2(a * a, b * b);
    }
}

// ---------------- pre-kernel 2: weight transform into staged layout --------------
__global__ void weight_prep_kernel(const float* __restrict__ mw0,
                                   const float* __restrict__ mwr,
                                   const float* __restrict__ vw0,
                                   const float* __restrict__ vwr,
                                   Sc2 sc2)
{
    const int idx = blockIdx.x * blockDim.x + threadIdx.x;   // over N_PERM*WSTRIDE
    if (idx >= N_PERM * WSTRIDE) return;
    const int p   = idx / WSTRIDE;
    const int rem = idx % WSTRIDE;
    const int s   = rem / (25 * 2 * KROW);
    const int j   = (rem / (2 * KROW)) % 25;
    const int k   = rem % (2 * KROW);

    float m = 0.0f, v = 0.0f;
    if (k < OP1) {
        const int gi = ((s * N_PERM + p) * OP1 + j) * OP1 + k;
        m = mwr[gi];
        v = expf(vwr[gi]) * sc2.v[k];
    }
    g_Wm[idx] = m;
    g_Wv[idx] = v;

    if (idx < N_PERM * 28) {
        const int p0 = idx / 28;
        const int k0 = idx % 28;
        float m0 = 0.0f, v0 = 0.0f;
        if (k0 < OP1) {
            m0 = mw0[p0 * OP1 + k0];
            v0 = expf(vw0[p0 * OP1 + k0]) * sc2.v[k0];
        }
        g_w0m[idx] = m0;
        g_w0v[idx] = v0;
    }
}

// ---------------- main kernel: one chain per block, 2 pts/thread, 2 point-tiles --
// blockIdx.z == 0: mean chain   v <- (v @ W) * B              -> out col 0
// blockIdx.z == 1: var chain    v <- (v @ (exp(W)*sc2)) * B^2 -> out col 1 (/post_prec)
__global__ __launch_bounds__(128, 4)
void bern_chain_kernel(const int*   __restrict__ perm,
                       const float* __restrict__ postp,
                       float*       __restrict__ out)
{
    __shared__ alignas(16) ull sW[7 * 25 * KROW];
    __shared__ alignas(16) ull sw0[KROW];
    __shared__ int   sperm[8];
    __shared__ float sscale;

    const int p   = blockIdx.y;
    const int VAR = blockIdx.z;
    const int tid = threadIdx.x;

    // var chain reads pre-squared basis; mean reads plain basis
    const float2* __restrict__ gB = VAR ? g_Bt2 : g_Bt;

    const int nbase = blockIdx.x * 512 + 2 * tid;   // tile0 point; tile1 = +256

    // --- issue tile0 stage-0 basis loads FIRST, overlapping with weight staging ---
    ulonglong2 bbv[KP];
    {
        const int d0 = perm[p * 8];                      // broadcast LDG
        const float2* bp0 = gB + d0 * (KP * N_PTS) + nbase;
        #pragma unroll
        for (int kk = 0; kk < KP; kk++)
            bbv[kk] = *(const ulonglong2*)(bp0 + kk * N_PTS);
    }

    // Weight staging: pure float4 copy from pre-transformed buffers.
    {
        const float4* __restrict__ wsrc =
            (const float4*)((VAR ? g_Wv : g_Wm) + p * WSTRIDE);
        float4* dst = (float4*)sW;
        #pragma unroll
        for (int t = tid; t < WSTRIDE / 4; t += 128)
            dst[t] = wsrc[t];
        if (tid < 7) {
            const float4* w0src =
                (const float4*)((VAR ? g_w0v : g_w0m) + p * 28);
            ((float4*)sw0)[tid] = w0src[tid];
        }
        if (tid < 8)  sperm[tid] = perm[p * 8 + tid];
        if (tid == 0) sscale = VAR ? 1.0f / postp[p] : 1.0f;
    }
    __syncthreads();

    // ---- two point-tiles share the staged weights ----
    #pragma unroll 1
    for (int t2 = 0; t2 < 2; t2++) {
        const int n0 = nbase + t2 * 256;

        if (t2 == 1) {   // tile0's bbv was preloaded before staging
            const float2* bp0 = gB + sperm[0] * (KP * N_PTS) + n0;
            #pragma unroll
            for (int kk = 0; kk < KP; kk++)
                bbv[kk] = *(const ulonglong2*)(bp0 + kk * N_PTS);
        }

        ull v0[KP], v1[KP];

        // stage 0 (basis resident in bbv)
        #pragma unroll
        for (int kk = 0; kk < KP; kk++) {
            v0[kk] = mul2(sw0[kk], bbv[kk].x);
            v1[kk] = mul2(sw0[kk], bbv[kk].y);
        }

        // stages 1..7 (rolled over s to stay inside I$)
        #pragma unroll 1
        for (int s = 0; s < 7; s++) {
            const float2* bp = gB + sperm[s + 1] * (KP * N_PTS) + n0;

            ull acc0[KP], acc1[KP];
            #pragma unroll
            for (int kk = 0; kk < KP; kk++) { acc0[kk] = 0ULL; acc1[kk] = 0ULL; }

            const ull* base = sW + s * 25 * KROW;

            #pragma unroll
            for (int j = 0; j < 25; j++) {
                // Hoisted epilogue loads: at j==13 half of v is dead; loads get
                // ~12 j-iterations of lead to cover L2 latency.
                if (j == 13) {
                    #pragma unroll
                    for (int kk = 0; kk < KP; kk++)
                        bbv[kk] = *(const ulonglong2*)(bp + kk * N_PTS);
                }
                const float a0 = (j & 1) ? hi2(v0[j >> 1]) : lo2(v0[j >> 1]);
                const float a1 = (j & 1) ? hi2(v1[j >> 1]) : lo2(v1[j >> 1]);
                const ull vj0 = dup2(a0);
                const ull vj1 = dup2(a1);
                const ull* rw = base + j * KROW;
                #pragma unroll
                for (int h = 0; h < 7; h++) {
                    const ulonglong2 w = *(const ulonglong2*)(rw + 2 * h);
                    acc0[2*h] = fma2(vj0, w.x, acc0[2*h]);
                    acc1[2*h] = fma2(vj1, w.x, acc1[2*h]);
                    if (2*h + 1 < KP) {
                        acc0[2*h + 1] = fma2(vj0, w.y, acc0[2*h + 1]);
                        acc1[2*h + 1] = fma2(vj1, w.y, acc1[2*h + 1]);
                    }
                }
            }

            // apply basis (registers already in flight from the j==13 hoist)
            #pragma unroll
            for (int kk = 0; kk < KP; kk++) {
                v0[kk] = mul2(acc0[kk], bbv[kk].x);
                v1[kk] = mul2(acc1[kk], bbv[kk].y);
            }
        }

        // reduce over k, then over p via atomics
        ull s0 = v0[0], s1 = v1[0];
        #pragma unroll
        for (int kk = 1; kk < KP; kk++) { s0 = add2(s0, v0[kk]); s1 = add2(s1, v1[kk]); }
        const float r0 = (lo2(s0) + hi2(s0)) * sscale;
        const float r1 = (lo2(s1) + hi2(s1)) * sscale;

        atomicAdd(out + 2 * n0 + VAR, r0);
        atomicAdd(out + 2 * (n0 + 1) + VAR, r1);
    }
}

// ---------------- host: sc2 = inv(B(I)^2) @ ones in double ----------------
static void compute_binom_d(double* bn) {
    bn[0] = 1.0;
    for (int k = 0; k < 24; k++) bn[k + 1] = bn[k] * (double)(24 - k) / (double)(k + 1);
}

static void compute_sc2_d(const double* bn, double* y) {
    double A[25][26];
    for (int i = 0; i < 25; i++) {
        const double t = (double)i / 24.0;
        const double q = 1.0 - t;
        double xp[25], qp[25];
        xp[0] = 1.0; for (int k = 1; k < 25; k++) xp[k] = xp[k - 1] * t;
        qp[0] = 1.0; for (int k = 1; k < 25; k++) qp[k] = qp[k - 1] * q;
        for (int k = 0; k < 25; k++) {
            const double B = bn[k] * xp[k] * qp[24 - k];
            A[i][k] = B * B;
        }
        A[i][25] = 1.0;   // rhs = ones
    }
    for (int c = 0; c < 25; c++) {
        int piv = c;
        for (int r = c + 1; r < 25; r++)
            if (fabs(A[r][c]) > fabs(A[piv][c])) piv = r;
        if (piv != c)
            for (int k = c; k < 26; k++) { double tmp = A[c][k]; A[c][k] = A[piv][k]; A[piv][k] = tmp; }
        const double inv = 1.0 / A[c][c];
        for (int r = 0; r < 25; r++) {
            if (r == c) continue;
            const double f = A[r][c] * inv;
            for (int k = c; k < 26; k++) A[r][k] -= f * A[c][k];
        }
    }
    for (int i = 0; i < 25; i++) y[i] = A[i][25] / A[i][i];
}

extern "C" void kernel_launch(void* const* d_in, const int* in_sizes, int n_in,
                              void* d_out, int out_size)
{
    const float* X    = (const float*)d_in[0];   // Xnew      (N, 8)
    const int*   perm = (const int*)  d_in[1];   // perm      (32, 8)
    const float* mw0  = (const float*)d_in[2];   // meanw0    (32, 1, 25)
    const float* mwr  = (const float*)d_in[3];   // meanw_rest(7, 32, 25, 25)
    const float* vw0  = (const float*)d_in[4];   // varw0     (32, 1, 25)
    const float* vwr  = (const float*)d_in[5];   // varw_rest (7, 32, 25, 25)
    const float* pp   = (const float*)d_in[6];   // post_prec (32,)
    float* out = (float*)d_out;                  // (N, 2) float32

    double bn_d[25], sc2_d[25];
    compute_binom_d(bn_d);
    compute_sc2_d(bn_d, sc2_d);

    Binom bn = {};
    Sc2   sc = {};
    for (int k = 0; k < 25; k++) {
        bn.b[k] = (float)bn_d[k];
        sc.v[k] = (float)sc2_d[k];
    }

    bern_prep_kernel<<<(N_DIM * N_PTS) / 256, 256>>>(X, out, bn);
    weight_prep_kernel<<<(N_PERM * WSTRIDE + 255) / 256, 256>>>(mw0, mwr, vw0, vwr, sc);

    dim3 grid(N_PTS / 512, N_PERM, 2);
    bern_chain_kernel<<<grid, 128>>>(perm, pp, out);
}